// round 16
// baseline (speedup 1.0000x reference)
#include <cuda_runtime.h>
#include <cstdint>

#define HH 96
#define WW 96
#define HW (HH*WW)
#define NB 8
#define SLICES 8
#define NBLK (NB*2*SLICES)       // 128 blocks: (sample, dir, slice)
#define NTHR 384                 // 12 warps
#define PTS_PER_BLK (HW/SLICES)  // 1152 = 384*3
#define ROWS_PER_SLICE (HH/SLICES)  // 12
#define NWORDS (HH*3)            // 288 tgt mask words
#define NSRCW (ROWS_PER_SLICE*3) // 36 src-slice mask words

__device__ float g_partials[NBLK];   // per-block directed-distance result (>=0)
__device__ int   g_done_s[NB];       // per-sample counters (to 16); self-reset
__device__ int   g_done = 0;         // sample-group counter (to 8); self-reset

__device__ __forceinline__ uint32_t pack16(uint32_t x) {
    // one valid low-nibble per byte -> compact to 16 contiguous bits
    x = (x | (x >> 4)) & 0x00FF00FFu;
    return (x | (x >> 8)) & 0x0000FFFFu;
}

// Branchless nearest set-bit distance to column c in a 96-bit row (row preloaded).
// Returns >= WW if row empty on both sides.
__device__ __forceinline__ int nearest_in_row(uint4 row,
                                              uint32_t mR0, uint32_t mR1, uint32_t mR2,
                                              uint32_t mL0, uint32_t mL1, uint32_t mL2,
                                              int c)
{
    const uint32_t r0 = row.x & mR0, r1 = row.y & mR1, r2 = row.z & mR2;
    int pR = r0 ? (__ffs(r0) - 1) : 1000;
    pR = min(pR, r1 ? (__ffs(r1) + 31) : 1000);
    pR = min(pR, r2 ? (__ffs(r2) + 63) : 1000);
    const uint32_t l0 = row.x & mL0, l1 = row.y & mL1, l2 = row.z & mL2;
    int pL = l0 ? (31 - __clz(l0)) : -1000;
    pL = max(pL, l1 ? (63 - __clz(l1)) : -1000);
    pL = max(pL, l2 ? (95 - __clz(l2)) : -1000);
    return min(pR - c, c - pL);
}

__device__ __forceinline__ uint32_t nib4(float4 v) {
    return (v.x > 0.5f ? 1u : 0u) | (v.y > 0.5f ? 2u : 0u)
         | (v.z > 0.5f ? 4u : 0u) | (v.w > 0.5f ? 8u : 0u);
}

__global__ void __launch_bounds__(NTHR)
hausdorff_kernel(const float* __restrict__ pred,
                 const float* __restrict__ targ,
                 float* __restrict__ out)
{
    __shared__ uint32_t s_nibT[HW / 16];     // 576 words: 1 nibble-byte per tgt float4
    __shared__ uint32_t s_nibS[NSRCW * 2];   // 72 words: 1 nibble-byte per src float4
    __shared__ uint32_t s_tgt[HH * 4];       // stride-4 rows, words 0..2 used, word 3 = 0
    __shared__ uint32_t s_srcw[NSRCW];       // raw src-image words for slice rows (stride 3)
    __shared__ float    s_red[NTHR / 32];
    __shared__ float    s_fin[NB];
    __shared__ int      s_last;

    const int blk   = blockIdx.x;
    const int slice = blk & (SLICES - 1);
    const int nd    = blk >> 3;          // n*2 + dir
    const int dir   = nd & 1;
    const int n     = nd >> 1;

    const int tid  = threadIdx.x;
    const int lane = tid & 31;
    const int warp = tid >> 5;

    if (tid == 0) s_last = 0;

    // dir 0: src img = pred(A), tgt img = targ(B);  dir 1: swapped
    const float* tgt_img = dir ? pred : targ;
    const float* src_img = dir ? targ : pred;
    const float4* pT4 = (const float4*)(tgt_img + n * HW);
    const float4* pS4 = (const float4*)(src_img + n * HW) + slice * (PTS_PER_BLK / 4);

    // ---- Phase 1: coalesced loads (lane i -> float4 i).
    // Target: full image (2304 float4 = 384*6). Source: slice rows only (288 float4).
    // inputs uniform [0,1): round(x) > 0.5  <=>  x > 0.5f  (0.5 ties round-even -> 0)
    uint8_t* nbT = (uint8_t*)s_nibT;
    uint8_t* nbS = (uint8_t*)s_nibS;
    #pragma unroll
    for (int k = 0; k < 6; ++k) {
        const int idx4 = tid + k * NTHR;
        nbT[idx4] = (uint8_t)nib4(pT4[idx4]);
    }
    if (tid < NSRCW * 8) {                       // 288 src float4
        nbS[tid] = (uint8_t)nib4(pS4[tid]);
    }
    __syncthreads();

    // ---- Phase 2: assemble mask words (8 staged bytes each)
    if (tid < NWORDS) {
        const uint2 w = ((const uint2*)s_nibT)[tid];
        const uint32_t a0 = w.x & 0x0F0F0F0Fu, a1 = w.y & 0x0F0F0F0Fu;
        const int row  = tid / 3;
        const int wcol = tid - row * 3;
        s_tgt[row * 4 + wcol] = pack16(a0) | (pack16(a1) << 16);
        if (wcol == 0) s_tgt[row * 4 + 3] = 0u;
    } else if (tid < NWORDS + NSRCW) {
        const int t = tid - NWORDS;
        const uint2 w = ((const uint2*)s_nibS)[t];
        const uint32_t a0 = w.x & 0x0F0F0F0Fu, a1 = w.y & 0x0F0F0F0Fu;
        s_srcw[t] = pack16(a0) | (pack16(a1) << 16);
    }
    __syncthreads();

    float lmax = -1.0f;   // max SQUARED distance; -1 = no src point seen

    #pragma unroll
    for (int k = 0; k < 3; ++k) {        // 1152 = 384 * 3
        const int pl = tid + k * NTHR;             // local point within slice
        const int rl = pl / WW;                    // local row 0..11
        const int c  = pl - rl * WW;
        const int r  = slice * ROWS_PER_SLICE + rl;
        const int k0 = c >> 5;
        const int s  = c & 31;
        // src = src_img & ~tgt_img at (r, c)
        const uint32_t sw = s_srcw[rl * 3 + k0] & ~s_tgt[r * 4 + k0];
        if (!((sw >> s) & 1u)) continue;

        // per-word right/left masks around column c (branchless selects)
        const uint32_t full = 0xFFFFFFFFu;
        const uint32_t hiR  = full << s;          // bits >= c within word k0
        const uint32_t loL  = (2u << s) - 1u;     // bits <= c within word k0
        const uint32_t mR0 = (k0 == 0) ? hiR : 0u;
        const uint32_t mR1 = (k0 < 1) ? full : ((k0 == 1) ? hiR : 0u);
        const uint32_t mR2 = (k0 < 2) ? full : hiR;
        const uint32_t mL0 = (k0 > 0) ? full : loL;
        const uint32_t mL1 = (k0 > 1) ? full : ((k0 == 1) ? loL : 0u);
        const uint32_t mL2 = (k0 == 2) ? loL : 0u;

        int best = 0x7FFFFFFF;

        // ---- Fast path: rows |dy| <= 1, 3 independent LDS.128 in one latency round
        {
            const int yu = r - 1, yd = r + 1;
            const uint4 rm = *(const uint4*)(s_tgt + r * 4);
            const uint4 ru = *(const uint4*)(s_tgt + max(yu, 0) * 4);
            const uint4 rd = *(const uint4*)(s_tgt + min(yd, HH - 1) * 4);
            const int dx0 = nearest_in_row(rm, mR0, mR1, mR2, mL0, mL1, mL2, c);
            if (dx0 < WW) best = dx0 * dx0;
            int dxu = nearest_in_row(ru, mR0, mR1, mR2, mL0, mL1, mL2, c);
            int dxd = nearest_in_row(rd, mR0, mR1, mR2, mL0, mL1, mL2, c);
            dxu = (yu >= 0) ? dxu : 10000;
            dxd = (yd < HH) ? dxd : 10000;
            const int m = min(dxu, dxd);
            if (m < WW) best = min(best, 1 + m * m);
        }

        // ---- Serial early-exit for rows |dy| >= 2 (only matters if best > 4)
        if (best > 4) {
            for (int d = 2; d < HH; ++d) {
                const int dd = d * d;
                if (dd >= best) break;
                const int yu = r - d, yd = r + d;
                if (yu >= 0) {
                    const uint4 row = *(const uint4*)(s_tgt + yu * 4);
                    const int dx = nearest_in_row(row, mR0, mR1, mR2, mL0, mL1, mL2, c);
                    if (dx < WW) best = min(best, dd + dx * dx);
                }
                if (yd < HH && dd < best) {
                    const uint4 row = *(const uint4*)(s_tgt + yd * 4);
                    const int dx = nearest_in_row(row, mR0, mR1, mR2, mL0, mL1, mL2, c);
                    if (dx < WW) best = min(best, dd + dx * dx);
                }
            }
        }

        // squared domain; 3e9 sentinel = "target set empty" (> any real squared dist)
        const float fsq = (best == 0x7FFFFFFF) ? 3e9f : (float)best;
        lmax = fmaxf(lmax, fsq);
    }

    // block max reduction (12 warps) -- squared domain
    for (int off = 16; off; off >>= 1)
        lmax = fmaxf(lmax, __shfl_xor_sync(0xFFFFFFFFu, lmax, off));
    if (lane == 0) s_red[warp] = lmax;
    __syncthreads();

    if (tid == 0) {
        float bm = s_red[0];
        #pragma unroll
        for (int i = 1; i < NTHR / 32; ++i) bm = fmaxf(bm, s_red[i]);
        // convert: empty src -> 0; empty tgt -> 1e9 (matches reference); else sqrt/96
        float v;
        if (bm < 0.0f)        v = 0.0f;
        else if (bm > 2e9f)   v = 1e9f;
        else                  v = sqrtf(bm) * (1.0f / 96.0f);
        g_partials[blk] = v;                       // plain STG, no round-trip
        __threadfence();
        // hierarchical completion: 16 blocks/sample (8 distinct counters), then 8 samples
        const int ps = atomicAdd(&g_done_s[n], 1);
        if (ps == 2 * SLICES - 1) {
            g_done_s[n] = 0;
            __threadfence();
            const int pg = atomicAdd(&g_done, 1);
            if (pg == NB - 1) { s_last = 1; g_done = 0; }
        }
    }
    __syncthreads();

    // ---- Parallel finisher: only the last-arriving block takes this path
    if (s_last) {
        float v = 0.0f;
        if (tid < NBLK)
            v = *(volatile float*)&g_partials[tid];   // 128 parallel L2 loads
        if (warp < NBLK / 32) {
            // 16 consecutive partials = one sample (both dirs x 8 slices).
            #pragma unroll
            for (int off = 8; off; off >>= 1)
                v = fmaxf(v, __shfl_xor_sync(0xFFFFFFFFu, v, off));
            if ((lane & 15) == 0)
                s_fin[(warp << 1) | (lane >> 4)] = v;  // 8 sample results
        }
        __syncthreads();
        if (tid == 0) {
            float sum = 0.0f;
            #pragma unroll
            for (int i = 0; i < NB; ++i) sum += s_fin[i];
            out[0] = sum * (1.0f / NB);
        }
    }
}

extern "C" void kernel_launch(void* const* d_in, const int* in_sizes, int n_in,
                              void* d_out, int out_size)
{
    (void)in_sizes; (void)n_in; (void)out_size;
    const float* pred = (const float*)d_in[0];
    const float* targ = (const float*)d_in[1];
    hausdorff_kernel<<<NBLK, NTHR>>>(pred, targ, (float*)d_out);
}